// round 9
// baseline (speedup 1.0000x reference)
#include <cuda_runtime.h>
#include <stdint.h>

// Problem constants (fixed by the dataset)
#define NN 100000      // nodes
#define EE 1600000     // edges
#define F0 128
#define F1 64
#define F2 40

// ---------------- scratch (static device globals; allocation-free) ----------
__device__ __align__(16) float g_h1s [NN * F1];   // (x @ W1) * invsqrt[row]
__device__ __align__(16) float g_agg1[NN * F1];   // sum of h1s[src] per dst
__device__ __align__(16) float g_h2s [NN * F2];   // (out1 @ W2) * invsqrt[row]
__device__ __align__(16) float g_agg2[NN * F2];   // sum of h2s[src] per dst
__device__ int   g_deg[NN];
__device__ int   g_off[NN + 1];
__device__ int   g_cursor[NN];
__device__ __align__(16) int g_csr_src[EE];       // srcs, edges sorted by dst
__device__ __align__(16) int g_csr_dst[EE];       // dsts, sorted (nondecreasing)
__device__ float g_invsqrt[NN];

// ---------------- helpers ---------------------------------------------------
__device__ __forceinline__ void red_add_v4(float* addr, float4 v) {
    asm volatile("red.global.add.v4.f32 [%0], {%1, %2, %3, %4};"
                 :: "l"(addr), "f"(v.x), "f"(v.y), "f"(v.z), "f"(v.w)
                 : "memory");
}
__device__ __forceinline__ float4 f4add(float4 a, float4 b) {
    return make_float4(a.x + b.x, a.y + b.y, a.z + b.z, a.w + b.w);
}

// ---------------- kernels ---------------------------------------------------

// Zero agg1, agg2 (as float4) and deg counters. Grid-stride.
__global__ void zero_kernel() {
    const int n1 = NN * (F1 / 4);
    const int n2 = NN * (F2 / 4);
    float4 z = make_float4(0.f, 0.f, 0.f, 0.f);
    for (int i = blockIdx.x * blockDim.x + threadIdx.x; i < n1 + n2;
         i += gridDim.x * blockDim.x) {
        if (i < n1) reinterpret_cast<float4*>(g_agg1)[i] = z;
        else        reinterpret_cast<float4*>(g_agg2)[i - n1] = z;
        if (i < NN) g_deg[i] = 0;
    }
}

// Degree histogram over dst; 2 edges per thread.
__global__ void deg_kernel(const int* __restrict__ dst, int E) {
    int i = (blockIdx.x * blockDim.x + threadIdx.x) * 2;
    if (i + 1 < E) {
        int2 d = *reinterpret_cast<const int2*>(dst + i);
        atomicAdd(&g_deg[d.x], 1);
        atomicAdd(&g_deg[d.y], 1);
    } else if (i < E) {
        atomicAdd(&g_deg[dst[i]], 1);
    }
}

// Single-block exclusive prefix scan of g_deg -> g_off / g_cursor + invsqrt.
__global__ __launch_bounds__(1024) void prefix_kernel() {
    __shared__ int ssum[1024];
    const int CH = (NN + 1023) / 1024;   // 98
    int t = threadIdx.x;
    int b = t * CH;
    int e = b + CH < NN ? b + CH : NN;
    if (b > NN) b = NN;

    int s = 0;
    for (int i = b; i < e; ++i) s += g_deg[i];
    ssum[t] = s;
    __syncthreads();

    for (int off = 1; off < 1024; off <<= 1) {
        int v = (t >= off) ? ssum[t - off] : 0;
        __syncthreads();
        ssum[t] += v;
        __syncthreads();
    }

    int run = ssum[t] - s;
    for (int i = b; i < e; ++i) {
        g_off[i]    = run;
        g_cursor[i] = run;
        int d = g_deg[i];
        run += d;
        g_invsqrt[i] = rsqrtf((float)(d + 1));
    }
    if (t == 1023) g_off[NN] = ssum[1023];
}

// Fill sorted edge list (src and dst) via cursor atomics; 2 edges per thread.
__global__ void fill_kernel(const int* __restrict__ src,
                            const int* __restrict__ dst, int E) {
    int i = (blockIdx.x * blockDim.x + threadIdx.x) * 2;
    if (i + 1 < E) {
        int2 d = *reinterpret_cast<const int2*>(dst + i);
        int2 s = *reinterpret_cast<const int2*>(src + i);
        int p0 = atomicAdd(&g_cursor[d.x], 1);
        int p1 = atomicAdd(&g_cursor[d.y], 1);
        g_csr_src[p0] = s.x;  g_csr_dst[p0] = d.x;
        g_csr_src[p1] = s.y;  g_csr_dst[p1] = d.y;
    } else if (i < E) {
        int dd = dst[i];
        int pos = atomicAdd(&g_cursor[dd], 1);
        g_csr_src[pos] = src[i];
        g_csr_dst[pos] = dd;
    }
}

// h1s = (x @ W1) * invsqrt[row]  — verified R7 tiled GEMM.
__global__ __launch_bounds__(256) void gemm1_kernel(const float* __restrict__ x,
                                                    const float* __restrict__ W1) {
    __shared__ float sX[64][68];
    __shared__ float sW[64 * F1];
    int tid = threadIdx.x;
    int row0 = blockIdx.x * 64;

    int tx = tid & 15;
    int ty = tid >> 4;

    float acc[4][4];
    #pragma unroll
    for (int r = 0; r < 4; ++r)
        #pragma unroll
        for (int c = 0; c < 4; ++c) acc[r][c] = 0.f;

    #pragma unroll
    for (int kc = 0; kc < 2; ++kc) {
        int k0 = kc * 64;

        const float4* w4g = reinterpret_cast<const float4*>(W1 + k0 * F1);
        #pragma unroll
        for (int i = 0; i < 4; ++i)
            reinterpret_cast<float4*>(sW)[tid + i * 256] = w4g[tid + i * 256];

        #pragma unroll
        for (int i = 0; i < 4; ++i) {
            int idx = tid + i * 256;
            int r   = idx >> 4;
            int k4  = idx & 15;
            int rr = row0 + r; if (rr >= NN) rr = NN - 1;
            float4 v = reinterpret_cast<const float4*>(
                           x + (size_t)rr * F0 + k0)[k4];
            sX[k4 * 4 + 0][r] = v.x;
            sX[k4 * 4 + 1][r] = v.y;
            sX[k4 * 4 + 2][r] = v.z;
            sX[k4 * 4 + 3][r] = v.w;
        }
        __syncthreads();

        #pragma unroll 4
        for (int k = 0; k < 64; ++k) {
            float4 xv = *reinterpret_cast<const float4*>(&sX[k][ty * 4]);
            float4 wv = *reinterpret_cast<const float4*>(&sW[k * F1 + tx * 4]);
            float xa[4] = {xv.x, xv.y, xv.z, xv.w};
            float wa[4] = {wv.x, wv.y, wv.z, wv.w};
            #pragma unroll
            for (int r = 0; r < 4; ++r)
                #pragma unroll
                for (int c = 0; c < 4; ++c)
                    acc[r][c] = fmaf(xa[r], wa[c], acc[r][c]);
        }
        __syncthreads();
    }

    #pragma unroll
    for (int r = 0; r < 4; ++r) {
        int rr = row0 + ty * 4 + r;
        if (rr < NN) {
            float sc = g_invsqrt[rr];
            *reinterpret_cast<float4*>(g_h1s + (size_t)rr * F1 + tx * 4) =
                make_float4(acc[r][0] * sc, acc[r][1] * sc,
                            acc[r][2] * sc, acc[r][3] * sc);
        }
    }
}

// Layer-1 scatter over dst-sorted edges with run-combining.
// Thread handles 4 consecutive sorted edges for one feature chunk (2 float4).
// 8 chunks per edge-group. Equal-dst runs are summed before a single RED.
__global__ __launch_bounds__(256) void scatter1_kernel(int E) {
    int i = blockIdx.x * blockDim.x + threadIdx.x;
    int ngroups = E >> 2;                  // E divisible by 4 (guarded below)
    int total = ngroups * 8;
    if (i >= total) return;
    int g = i >> 3;
    int c = (i & 7) * 2;                   // float4 index pair: c, c+1
    int e0 = g * 4;

    int4 ds = *reinterpret_cast<const int4*>(g_csr_dst + e0);
    int4 ss = *reinterpret_cast<const int4*>(g_csr_src + e0);
    int d[4] = {ds.x, ds.y, ds.z, ds.w};
    int s[4] = {ss.x, ss.y, ss.z, ss.w};

    float4 va[4], vb[4];
    #pragma unroll
    for (int j = 0; j < 4; ++j) {
        const float4* hp = reinterpret_cast<const float4*>(g_h1s + (size_t)s[j] * F1) + c;
        va[j] = hp[0];
        vb[j] = hp[1];
    }

    int curd = d[0];
    float4 a = va[0], b = vb[0];
    #pragma unroll
    for (int j = 1; j < 4; ++j) {
        if (d[j] == curd) {
            a = f4add(a, va[j]);
            b = f4add(b, vb[j]);
        } else {
            float* ap = g_agg1 + (size_t)curd * F1 + c * 4;
            red_add_v4(ap, a);
            red_add_v4(ap + 4, b);
            curd = d[j]; a = va[j]; b = vb[j];
        }
    }
    float* ap = g_agg1 + (size_t)curd * F1 + c * 4;
    red_add_v4(ap, a);
    red_add_v4(ap + 4, b);
}

// Tail edges (if E % 4 != 0): plain per-edge scatter, 8 threads/edge.
__global__ void scatter1_tail_kernel(int E) {
    int base = E & ~3;
    int rem = E - base;
    int i = blockIdx.x * blockDim.x + threadIdx.x;
    if (i >= rem * 8) return;
    int e = base + (i >> 3);
    int c = (i & 7) * 2;
    int s = g_csr_src[e];
    int d = g_csr_dst[e];
    const float4* hp = reinterpret_cast<const float4*>(g_h1s + (size_t)s * F1) + c;
    float* ap = g_agg1 + (size_t)d * F1 + c * 4;
    red_add_v4(ap, hp[0]);
    red_add_v4(ap + 4, hp[1]);
}

// out1 = relu(invsqrt_d * (agg1 + h1s));  h2s = (out1 @ W2) * invsqrt_d.
__global__ __launch_bounds__(128) void fuse2_kernel(const float* __restrict__ W2) {
    __shared__ float sW[F1 * F2];
    int tid = threadIdx.x;
    for (int i = tid; i < F1 * F2; i += 128) sW[i] = W2[i];
    __syncthreads();

    int row = blockIdx.x * 128 + tid;
    if (row >= NN) return;

    float inv_d = g_invsqrt[row];

    float o[F1];
    const float4* ag = reinterpret_cast<const float4*>(g_agg1 + (size_t)row * F1);
    const float4* hr = reinterpret_cast<const float4*>(g_h1s  + (size_t)row * F1);
    #pragma unroll
    for (int j = 0; j < F1 / 4; ++j) {
        float4 a = ag[j];
        float4 h = hr[j];
        o[4*j+0] = fmaxf(inv_d * (a.x + h.x), 0.f);
        o[4*j+1] = fmaxf(inv_d * (a.y + h.y), 0.f);
        o[4*j+2] = fmaxf(inv_d * (a.z + h.z), 0.f);
        o[4*j+3] = fmaxf(inv_d * (a.w + h.w), 0.f);
    }

    float acc[F2];
    #pragma unroll
    for (int j = 0; j < F2; ++j) acc[j] = 0.f;

    #pragma unroll 4
    for (int k = 0; k < F1; ++k) {
        float ov = o[k];
        const float4* w4 = reinterpret_cast<const float4*>(sW + k * F2);
        #pragma unroll
        for (int j = 0; j < F2 / 4; ++j) {
            float4 w = w4[j];
            acc[4*j+0] = fmaf(ov, w.x, acc[4*j+0]);
            acc[4*j+1] = fmaf(ov, w.y, acc[4*j+1]);
            acc[4*j+2] = fmaf(ov, w.z, acc[4*j+2]);
            acc[4*j+3] = fmaf(ov, w.w, acc[4*j+3]);
        }
    }
    float4* out = reinterpret_cast<float4*>(g_h2s + (size_t)row * F2);
    #pragma unroll
    for (int j = 0; j < F2 / 4; ++j)
        out[j] = make_float4(acc[4*j]*inv_d, acc[4*j+1]*inv_d,
                             acc[4*j+2]*inv_d, acc[4*j+3]*inv_d);
}

// Layer-2 scatter over dst-sorted edges with run-combining.
// Thread handles 4 consecutive edges for one of 5 chunks (2 float4 each).
__global__ __launch_bounds__(256) void scatter2_kernel(int E) {
    int i = blockIdx.x * blockDim.x + threadIdx.x;
    int ngroups = E >> 2;
    int total = ngroups * 5;
    if (i >= total) return;
    int g = i / 5;
    int c = (i - g * 5) * 2;               // float4 index pair
    int e0 = g * 4;

    int4 ds = *reinterpret_cast<const int4*>(g_csr_dst + e0);
    int4 ss = *reinterpret_cast<const int4*>(g_csr_src + e0);
    int d[4] = {ds.x, ds.y, ds.z, ds.w};
    int s[4] = {ss.x, ss.y, ss.z, ss.w};

    float4 va[4], vb[4];
    #pragma unroll
    for (int j = 0; j < 4; ++j) {
        const float4* hp = reinterpret_cast<const float4*>(g_h2s + (size_t)s[j] * F2) + c;
        va[j] = hp[0];
        vb[j] = hp[1];
    }

    int curd = d[0];
    float4 a = va[0], b = vb[0];
    #pragma unroll
    for (int j = 1; j < 4; ++j) {
        if (d[j] == curd) {
            a = f4add(a, va[j]);
            b = f4add(b, vb[j]);
        } else {
            float* ap = g_agg2 + (size_t)curd * F2 + c * 4;
            red_add_v4(ap, a);
            red_add_v4(ap + 4, b);
            curd = d[j]; a = va[j]; b = vb[j];
        }
    }
    float* ap = g_agg2 + (size_t)curd * F2 + c * 4;
    red_add_v4(ap, a);
    red_add_v4(ap + 4, b);
}

__global__ void scatter2_tail_kernel(int E) {
    int base = E & ~3;
    int rem = E - base;
    int i = blockIdx.x * blockDim.x + threadIdx.x;
    if (i >= rem * 5) return;
    int e = base + i / 5;
    int c = (i % 5) * 2;
    int s = g_csr_src[e];
    int d = g_csr_dst[e];
    const float4* hp = reinterpret_cast<const float4*>(g_h2s + (size_t)s * F2) + c;
    float* ap = g_agg2 + (size_t)d * F2 + c * 4;
    red_add_v4(ap, hp[0]);
    red_add_v4(ap + 4, hp[1]);
}

// out = relu(invsqrt_d * (agg2 + h2s))
__global__ __launch_bounds__(256) void final_kernel(float* __restrict__ out) {
    int i = blockIdx.x * blockDim.x + threadIdx.x;
    const int total = NN * (F2 / 4);
    if (i >= total) return;
    int node = i / 10;
    float inv_d = g_invsqrt[node];
    float4 a = reinterpret_cast<const float4*>(g_agg2)[i];
    float4 h = reinterpret_cast<const float4*>(g_h2s)[i];
    float4 r;
    r.x = fmaxf(inv_d * (a.x + h.x), 0.f);
    r.y = fmaxf(inv_d * (a.y + h.y), 0.f);
    r.z = fmaxf(inv_d * (a.z + h.z), 0.f);
    r.w = fmaxf(inv_d * (a.w + h.w), 0.f);
    reinterpret_cast<float4*>(out)[i] = r;
}

// ---------------- launch ----------------------------------------------------
extern "C" void kernel_launch(void* const* d_in, const int* in_sizes, int n_in,
                              void* d_out, int out_size) {
    const float* x  = (const float*)d_in[0];   // [N,128]
    const int*   ei = (const int*)  d_in[1];   // [2,E]
    const float* W1 = (const float*)d_in[2];   // [128,64]
    const float* W2 = (const float*)d_in[3];   // [64,40]
    float* out = (float*)d_out;

    int E = in_sizes[1] / 2;
    const int* src = ei;
    const int* dst = ei + E;

    // build: zero + degree + scan(+invsqrt) + sorted edge list
    zero_kernel  <<<2048, 256>>>();
    deg_kernel   <<<(E/2 + 255) / 256, 256>>>(dst, E);
    prefix_kernel<<<1, 1024>>>();
    fill_kernel  <<<(E/2 + 255) / 256, 256>>>(src, dst, E);

    // layer 1
    gemm1_kernel <<<(NN + 63) / 64, 256>>>(x, W1);
    {
        int total = (E >> 2) * 8;
        scatter1_kernel<<<(total + 255) / 256, 256>>>(E);
        if (E & 3) scatter1_tail_kernel<<<1, 256>>>(E);
    }
    fuse2_kernel <<<(NN + 127) / 128, 128>>>(W2);

    // layer 2
    {
        int total = (E >> 2) * 5;
        scatter2_kernel<<<(total + 255) / 256, 256>>>(E);
        if (E & 3) scatter2_tail_kernel<<<1, 256>>>(E);
    }
    final_kernel <<<(NN * (F2/4) + 255) / 256, 256>>>(out);
}

// round 10
// speedup vs baseline: 1.5089x; 1.5089x over previous
#include <cuda_runtime.h>
#include <stdint.h>

// Problem constants (fixed by the dataset)
#define NN 100000      // nodes
#define F0 128
#define F1 64
#define F2 40

// ---------------- scratch (static device globals; allocation-free) ----------
__device__ __align__(16) float g_h1s [NN * F1];   // (x @ W1) * invsqrt[row]
__device__ __align__(16) float g_agg1[NN * F1];   // sum of h1s[src] per dst
__device__ __align__(16) float g_h2s [NN * F2];   // (out1 @ W2) * invsqrt[row]
__device__ __align__(16) float g_agg2[NN * F2];   // sum of h2s[src] per dst
__device__ int   g_deg[NN];
__device__ float g_invsqrt[NN];

// ---------------- helpers ---------------------------------------------------
__device__ __forceinline__ void red_add_v4(float* addr, float4 v) {
    asm volatile("red.global.add.v4.f32 [%0], {%1, %2, %3, %4};"
                 :: "l"(addr), "f"(v.x), "f"(v.y), "f"(v.z), "f"(v.w)
                 : "memory");
}

// ---------------- kernels ---------------------------------------------------

// Zero deg counters only (agg zeroing folded into gemm1/fuse2 epilogues).
__global__ void zero_kernel() {
    int i = blockIdx.x * blockDim.x + threadIdx.x;
    if (i < NN) g_deg[i] = 0;
}

// Degree histogram over dst (self-loop added later as +1).
__global__ void deg_kernel(const int* __restrict__ dst, int E) {
    int i = blockIdx.x * blockDim.x + threadIdx.x;
    if (i < E) atomicAdd(&g_deg[dst[i]], 1);
}

__global__ void invsqrt_kernel() {
    int i = blockIdx.x * blockDim.x + threadIdx.x;
    if (i < NN) g_invsqrt[i] = rsqrtf((float)(g_deg[i] + 1));
}

// h1s = (x @ W1) * invsqrt[row]   (100000x128 @ 128x64), fp32.
// 128 threads, block tile 128 rows x 64 cols, 8x8 micro-tile, k-chunks of 32.
// Thread (tx,ty): cols {tx*4..+3, 32+tx*4..+3}, rows {ty*4..+3, 64+ty*4..+3}.
// Epilogue also zeros the matching agg1 slots.
__global__ __launch_bounds__(128) void gemm1_kernel(const float* __restrict__ x,
                                                    const float* __restrict__ W1) {
    __shared__ float sX[32][132];           // [k_local][row 0..127], padded pitch
    __shared__ float sW[32 * F1];           // [k_local][col], 8 KB
    int tid = threadIdx.x;
    int row0 = blockIdx.x * 128;

    int tx = tid & 7;                       // col groups: tx*4 and 32+tx*4
    int ty = tid >> 3;                      // row groups: ty*4 and 64+ty*4 (ty 0..15)

    float acc[8][8];
    #pragma unroll
    for (int r = 0; r < 8; ++r)
        #pragma unroll
        for (int c = 0; c < 8; ++c) acc[r][c] = 0.f;

    #pragma unroll
    for (int kc = 0; kc < 4; ++kc) {
        int k0 = kc * 32;

        // W chunk: 32 k-rows x 64 cols = 512 float4; 4 per thread
        const float4* w4g = reinterpret_cast<const float4*>(W1 + k0 * F1);
        #pragma unroll
        for (int i = 0; i < 4; ++i)
            reinterpret_cast<float4*>(sW)[tid + i * 128] = w4g[tid + i * 128];

        // x chunk: 128 rows x 32 k = 1024 float4; 8 per thread, transposed store
        #pragma unroll
        for (int i = 0; i < 8; ++i) {
            int idx = tid + i * 128;        // 0..1023
            int r   = idx >> 3;             // 0..127
            int k4  = idx & 7;              // 0..7 (float4 along k)
            int rr = row0 + r; if (rr >= NN) rr = NN - 1;
            float4 v = reinterpret_cast<const float4*>(
                           x + (size_t)rr * F0 + k0)[k4];
            sX[k4 * 4 + 0][r] = v.x;
            sX[k4 * 4 + 1][r] = v.y;
            sX[k4 * 4 + 2][r] = v.z;
            sX[k4 * 4 + 3][r] = v.w;
        }
        __syncthreads();

        #pragma unroll 2
        for (int k = 0; k < 32; ++k) {
            float4 xv0 = *reinterpret_cast<const float4*>(&sX[k][ty * 4]);
            float4 xv1 = *reinterpret_cast<const float4*>(&sX[k][64 + ty * 4]);
            float4 wv0 = *reinterpret_cast<const float4*>(&sW[k * F1 + tx * 4]);
            float4 wv1 = *reinterpret_cast<const float4*>(&sW[k * F1 + 32 + tx * 4]);
            float xa[8] = {xv0.x, xv0.y, xv0.z, xv0.w, xv1.x, xv1.y, xv1.z, xv1.w};
            float wa[8] = {wv0.x, wv0.y, wv0.z, wv0.w, wv1.x, wv1.y, wv1.z, wv1.w};
            #pragma unroll
            for (int r = 0; r < 8; ++r)
                #pragma unroll
                for (int c = 0; c < 8; ++c)
                    acc[r][c] = fmaf(xa[r], wa[c], acc[r][c]);
        }
        __syncthreads();
    }

    float4 z = make_float4(0.f, 0.f, 0.f, 0.f);
    #pragma unroll
    for (int r = 0; r < 8; ++r) {
        int rr = row0 + ((r < 4) ? (ty * 4 + r) : (64 + ty * 4 + r - 4));
        if (rr < NN) {
            float sc = g_invsqrt[rr];
            float* hb = g_h1s  + (size_t)rr * F1;
            float* ab = g_agg1 + (size_t)rr * F1;
            *reinterpret_cast<float4*>(hb + tx * 4) =
                make_float4(acc[r][0]*sc, acc[r][1]*sc, acc[r][2]*sc, acc[r][3]*sc);
            *reinterpret_cast<float4*>(hb + 32 + tx * 4) =
                make_float4(acc[r][4]*sc, acc[r][5]*sc, acc[r][6]*sc, acc[r][7]*sc);
            *reinterpret_cast<float4*>(ab + tx * 4)      = z;
            *reinterpret_cast<float4*>(ab + 32 + tx * 4) = z;
        }
    }
}

// Layer-1 scatter: agg1[dst] += h1s[src].  8 threads/edge, 2 float4 each.
// (verified R7 kernel, unchanged)
__global__ __launch_bounds__(256) void scatter1_kernel(const int* __restrict__ src,
                                                       const int* __restrict__ dst, int E) {
    int i = blockIdx.x * blockDim.x + threadIdx.x;
    int total = E * 8;
    if (i >= total) return;
    int e = i >> 3;
    int c = (i & 7) * 2;
    int s = __ldg(src + e);
    int d = __ldg(dst + e);
    const float4* hp = reinterpret_cast<const float4*>(g_h1s + (size_t)s * F1) + c;
    float*        ap = g_agg1 + (size_t)d * F1 + c * 4;
    float4 v0 = hp[0];
    float4 v1 = hp[1];
    red_add_v4(ap,     v0);
    red_add_v4(ap + 4, v1);
}

// out1 = relu(invsqrt_d * (agg1 + h1s));  h2s = (out1 @ W2) * invsqrt_d.
// Also zeros this row's agg2 slots (runs before scatter2).
__global__ __launch_bounds__(128) void fuse2_kernel(const float* __restrict__ W2) {
    __shared__ float sW[F1 * F2];
    int tid = threadIdx.x;
    for (int i = tid; i < F1 * F2; i += 128) sW[i] = W2[i];
    __syncthreads();

    int row = blockIdx.x * 128 + tid;
    if (row >= NN) return;

    float inv_d = g_invsqrt[row];

    float o[F1];
    const float4* ag = reinterpret_cast<const float4*>(g_agg1 + (size_t)row * F1);
    const float4* hr = reinterpret_cast<const float4*>(g_h1s  + (size_t)row * F1);
    #pragma unroll
    for (int j = 0; j < F1 / 4; ++j) {
        float4 a = ag[j];
        float4 h = hr[j];
        o[4*j+0] = fmaxf(inv_d * (a.x + h.x), 0.f);
        o[4*j+1] = fmaxf(inv_d * (a.y + h.y), 0.f);
        o[4*j+2] = fmaxf(inv_d * (a.z + h.z), 0.f);
        o[4*j+3] = fmaxf(inv_d * (a.w + h.w), 0.f);
    }

    float acc[F2];
    #pragma unroll
    for (int j = 0; j < F2; ++j) acc[j] = 0.f;

    #pragma unroll 4
    for (int k = 0; k < F1; ++k) {
        float ov = o[k];
        const float4* w4 = reinterpret_cast<const float4*>(sW + k * F2);
        #pragma unroll
        for (int j = 0; j < F2 / 4; ++j) {
            float4 w = w4[j];
            acc[4*j+0] = fmaf(ov, w.x, acc[4*j+0]);
            acc[4*j+1] = fmaf(ov, w.y, acc[4*j+1]);
            acc[4*j+2] = fmaf(ov, w.z, acc[4*j+2]);
            acc[4*j+3] = fmaf(ov, w.w, acc[4*j+3]);
        }
    }
    float4* out = reinterpret_cast<float4*>(g_h2s + (size_t)row * F2);
    float4* az  = reinterpret_cast<float4*>(g_agg2 + (size_t)row * F2);
    float4 z = make_float4(0.f, 0.f, 0.f, 0.f);
    #pragma unroll
    for (int j = 0; j < F2 / 4; ++j) {
        out[j] = make_float4(acc[4*j]*inv_d, acc[4*j+1]*inv_d,
                             acc[4*j+2]*inv_d, acc[4*j+3]*inv_d);
        az[j] = z;
    }
}

// Layer-2 scatter: agg2[dst] += h2s[src].  5 threads/edge, 2 float4 each.
// (verified R7 kernel, unchanged)
__global__ __launch_bounds__(256) void scatter2_kernel(const int* __restrict__ src,
                                                       const int* __restrict__ dst, int E) {
    int i = blockIdx.x * blockDim.x + threadIdx.x;
    int total = E * 5;
    if (i >= total) return;
    int e = i / 5;
    int c = (i - e * 5) * 2;
    int s = __ldg(src + e);
    int d = __ldg(dst + e);
    const float4* hp = reinterpret_cast<const float4*>(g_h2s + (size_t)s * F2) + c;
    float*        ap = g_agg2 + (size_t)d * F2 + c * 4;
    float4 v0 = hp[0];
    float4 v1 = hp[1];
    red_add_v4(ap,     v0);
    red_add_v4(ap + 4, v1);
}

// out = relu(invsqrt_d * (agg2 + h2s))
__global__ __launch_bounds__(256) void final_kernel(float* __restrict__ out) {
    int i = blockIdx.x * blockDim.x + threadIdx.x;
    const int total = NN * (F2 / 4);
    if (i >= total) return;
    int node = i / 10;
    float inv_d = g_invsqrt[node];
    float4 a = reinterpret_cast<const float4*>(g_agg2)[i];
    float4 h = reinterpret_cast<const float4*>(g_h2s)[i];
    float4 r;
    r.x = fmaxf(inv_d * (a.x + h.x), 0.f);
    r.y = fmaxf(inv_d * (a.y + h.y), 0.f);
    r.z = fmaxf(inv_d * (a.z + h.z), 0.f);
    r.w = fmaxf(inv_d * (a.w + h.w), 0.f);
    reinterpret_cast<float4*>(out)[i] = r;
}

// ---------------- launch ----------------------------------------------------
extern "C" void kernel_launch(void* const* d_in, const int* in_sizes, int n_in,
                              void* d_out, int out_size) {
    const float* x  = (const float*)d_in[0];   // [N,128]
    const int*   ei = (const int*)  d_in[1];   // [2,E]
    const float* W1 = (const float*)d_in[2];   // [128,64]
    const float* W2 = (const float*)d_in[3];   // [64,40]
    float* out = (float*)d_out;

    int E = in_sizes[1] / 2;
    const int* src = ei;
    const int* dst = ei + E;

    // 1. zero deg (agg zeroing folded into gemm1/fuse2)
    zero_kernel<<<(NN + 255) / 256, 256>>>();
    // 2. degree histogram
    deg_kernel<<<(E + 255) / 256, 256>>>(dst, E);
    // 3. inv sqrt
    invsqrt_kernel<<<(NN + 255) / 256, 256>>>();
    // 4. h1s = (x @ W1) * invsqrt  (8x8 micro-tile GEMM; also zeros agg1)
    gemm1_kernel<<<(NN + 127) / 128, 128>>>(x, W1);
    // 5. layer-1 edge scatter
    scatter1_kernel<<<(E * 8 + 255) / 256, 256>>>(src, dst, E);
    // 6. relu + self term + GEMM2 -> h2s (also zeros agg2)
    fuse2_kernel<<<(NN + 127) / 128, 128>>>(W2);
    // 7. layer-2 edge scatter
    scatter2_kernel<<<(E * 5 + 255) / 256, 256>>>(src, dst, E);
    // 8. final relu -> d_out
    final_kernel<<<(NN * (F2/4) + 255) / 256, 256>>>(out);
}

// round 12
// speedup vs baseline: 1.5413x; 1.0215x over previous
#include <cuda_runtime.h>
#include <stdint.h>

// Problem constants (fixed by the dataset)
#define NN 100000      // nodes
#define F0 128
#define F1 64
#define F2 40

// ---------------- scratch (static device globals; allocation-free) ----------
__device__ __align__(16) float g_h1s [NN * F1];   // (x @ W1) * invsqrt[row]
__device__ __align__(16) float g_agg1[NN * F1];   // sum of h1s[src] per dst
__device__ __align__(16) float g_h2s [NN * F2];   // (out1 @ W2) * invsqrt[row]
__device__ __align__(16) float g_agg2[NN * F2];   // sum of h2s[src] per dst
__device__ int   g_deg[NN];

// ---------------- helpers ---------------------------------------------------
__device__ __forceinline__ void red_add_v4(float* addr, float4 v) {
    asm volatile("red.global.add.v4.f32 [%0], {%1, %2, %3, %4};"
                 :: "l"(addr), "f"(v.x), "f"(v.y), "f"(v.z), "f"(v.w)
                 : "memory");
}
__device__ __forceinline__ float inv_sqrt_deg(int node) {
    return rsqrtf((float)(g_deg[node] + 1));
}

// ---------------- kernels ---------------------------------------------------

// 1st launch: zero deg counters (agg zeroing folded into gemm1/fuse2).
__global__ void zero_kernel() {
    int i = blockIdx.x * blockDim.x + threadIdx.x;
    if (i < NN) g_deg[i] = 0;
}

// 2nd launch: degree histogram over dst; 2 edges per thread.
__global__ void deg_kernel(const int* __restrict__ dst, int E) {
    int i = (blockIdx.x * blockDim.x + threadIdx.x) * 2;
    if (i + 1 < E) {
        int2 d = *reinterpret_cast<const int2*>(dst + i);
        atomicAdd(&g_deg[d.x], 1);
        atomicAdd(&g_deg[d.y], 1);
    } else if (i < E) {
        atomicAdd(&g_deg[dst[i]], 1);
    }
}

// 3rd launch: h1s = (x @ W1) * rsqrt(deg+1)  (verified R10 8x8-tile GEMM).
// Epilogue also zeros the matching agg1 slots.
__global__ __launch_bounds__(128) void gemm1_kernel(const float* __restrict__ x,
                                                    const float* __restrict__ W1) {
    __shared__ float sX[32][132];           // [k_local][row 0..127], padded pitch
    __shared__ float sW[32 * F1];           // [k_local][col], 8 KB
    int tid = threadIdx.x;
    int row0 = blockIdx.x * 128;

    int tx = tid & 7;                       // col groups: tx*4 and 32+tx*4
    int ty = tid >> 3;                      // row groups: ty*4 and 64+ty*4

    float acc[8][8];
    #pragma unroll
    for (int r = 0; r < 8; ++r)
        #pragma unroll
        for (int c = 0; c < 8; ++c) acc[r][c] = 0.f;

    #pragma unroll
    for (int kc = 0; kc < 4; ++kc) {
        int k0 = kc * 32;

        const float4* w4g = reinterpret_cast<const float4*>(W1 + k0 * F1);
        #pragma unroll
        for (int i = 0; i < 4; ++i)
            reinterpret_cast<float4*>(sW)[tid + i * 128] = w4g[tid + i * 128];

        #pragma unroll
        for (int i = 0; i < 8; ++i) {
            int idx = tid + i * 128;
            int r   = idx >> 3;
            int k4  = idx & 7;
            int rr = row0 + r; if (rr >= NN) rr = NN - 1;
            float4 v = reinterpret_cast<const float4*>(
                           x + (size_t)rr * F0 + k0)[k4];
            sX[k4 * 4 + 0][r] = v.x;
            sX[k4 * 4 + 1][r] = v.y;
            sX[k4 * 4 + 2][r] = v.z;
            sX[k4 * 4 + 3][r] = v.w;
        }
        __syncthreads();

        #pragma unroll 2
        for (int k = 0; k < 32; ++k) {
            float4 xv0 = *reinterpret_cast<const float4*>(&sX[k][ty * 4]);
            float4 xv1 = *reinterpret_cast<const float4*>(&sX[k][64 + ty * 4]);
            float4 wv0 = *reinterpret_cast<const float4*>(&sW[k * F1 + tx * 4]);
            float4 wv1 = *reinterpret_cast<const float4*>(&sW[k * F1 + 32 + tx * 4]);
            float xa[8] = {xv0.x, xv0.y, xv0.z, xv0.w, xv1.x, xv1.y, xv1.z, xv1.w};
            float wa[8] = {wv0.x, wv0.y, wv0.z, wv0.w, wv1.x, wv1.y, wv1.z, wv1.w};
            #pragma unroll
            for (int r = 0; r < 8; ++r)
                #pragma unroll
                for (int c = 0; c < 8; ++c)
                    acc[r][c] = fmaf(xa[r], wa[c], acc[r][c]);
        }
        __syncthreads();
    }

    float4 z = make_float4(0.f, 0.f, 0.f, 0.f);
    #pragma unroll
    for (int r = 0; r < 8; ++r) {
        int rr = row0 + ((r < 4) ? (ty * 4 + r) : (64 + ty * 4 + r - 4));
        if (rr < NN) {
            float sc = inv_sqrt_deg(rr);
            float* hb = g_h1s  + (size_t)rr * F1;
            float* ab = g_agg1 + (size_t)rr * F1;
            *reinterpret_cast<float4*>(hb + tx * 4) =
                make_float4(acc[r][0]*sc, acc[r][1]*sc, acc[r][2]*sc, acc[r][3]*sc);
            *reinterpret_cast<float4*>(hb + 32 + tx * 4) =
                make_float4(acc[r][4]*sc, acc[r][5]*sc, acc[r][6]*sc, acc[r][7]*sc);
            *reinterpret_cast<float4*>(ab + tx * 4)      = z;
            *reinterpret_cast<float4*>(ab + 32 + tx * 4) = z;
        }
    }
}

// 4th launch (PROFILED): layer-1 scatter agg1[dst] += h1s[src].
// 8 threads/edge, 2 float4 each. (verified R7 kernel, unchanged)
__global__ __launch_bounds__(256) void scatter1_kernel(const int* __restrict__ src,
                                                       const int* __restrict__ dst, int E) {
    int i = blockIdx.x * blockDim.x + threadIdx.x;
    int total = E * 8;
    if (i >= total) return;
    int e = i >> 3;
    int c = (i & 7) * 2;
    int s = __ldg(src + e);
    int d = __ldg(dst + e);
    const float4* hp = reinterpret_cast<const float4*>(g_h1s + (size_t)s * F1) + c;
    float*        ap = g_agg1 + (size_t)d * F1 + c * 4;
    float4 v0 = hp[0];
    float4 v1 = hp[1];
    red_add_v4(ap,     v0);
    red_add_v4(ap + 4, v1);
}

// out1 = relu(inv_d * (agg1 + h1s));  h2s = (out1 @ W2) * inv_d.
// Also zeros this row's agg2 slots (runs before scatter2).
__global__ __launch_bounds__(256) void fuse2_kernel(const float* __restrict__ W2) {
    __shared__ float sW[F1 * F2];
    int tid = threadIdx.x;
    for (int i = tid; i < F1 * F2; i += 256) sW[i] = W2[i];
    __syncthreads();

    int row = blockIdx.x * 256 + tid;
    if (row >= NN) return;

    float inv_d = inv_sqrt_deg(row);

    float o[F1];
    const float4* ag = reinterpret_cast<const float4*>(g_agg1 + (size_t)row * F1);
    const float4* hr = reinterpret_cast<const float4*>(g_h1s  + (size_t)row * F1);
    #pragma unroll
    for (int j = 0; j < F1 / 4; ++j) {
        float4 a = ag[j];
        float4 h = hr[j];
        o[4*j+0] = fmaxf(inv_d * (a.x + h.x), 0.f);
        o[4*j+1] = fmaxf(inv_d * (a.y + h.y), 0.f);
        o[4*j+2] = fmaxf(inv_d * (a.z + h.z), 0.f);
        o[4*j+3] = fmaxf(inv_d * (a.w + h.w), 0.f);
    }

    float acc[F2];
    #pragma unroll
    for (int j = 0; j < F2; ++j) acc[j] = 0.f;

    #pragma unroll 4
    for (int k = 0; k < F1; ++k) {
        float ov = o[k];
        const float4* w4 = reinterpret_cast<const float4*>(sW + k * F2);
        #pragma unroll
        for (int j = 0; j < F2 / 4; ++j) {
            float4 w = w4[j];
            acc[4*j+0] = fmaf(ov, w.x, acc[4*j+0]);
            acc[4*j+1] = fmaf(ov, w.y, acc[4*j+1]);
            acc[4*j+2] = fmaf(ov, w.z, acc[4*j+2]);
            acc[4*j+3] = fmaf(ov, w.w, acc[4*j+3]);
        }
    }
    float4* out = reinterpret_cast<float4*>(g_h2s + (size_t)row * F2);
    float4* az  = reinterpret_cast<float4*>(g_agg2 + (size_t)row * F2);
    float4 z = make_float4(0.f, 0.f, 0.f, 0.f);
    #pragma unroll
    for (int j = 0; j < F2 / 4; ++j) {
        out[j] = make_float4(acc[4*j]*inv_d, acc[4*j+1]*inv_d,
                             acc[4*j+2]*inv_d, acc[4*j+3]*inv_d);
        az[j] = z;
    }
}

// Layer-2 scatter: agg2[dst] += h2s[src].  5 threads/edge, 2 float4 each.
// (verified R7 kernel, unchanged)
__global__ __launch_bounds__(256) void scatter2_kernel(const int* __restrict__ src,
                                                       const int* __restrict__ dst, int E) {
    int i = blockIdx.x * blockDim.x + threadIdx.x;
    int total = E * 5;
    if (i >= total) return;
    int e = i / 5;
    int c = (i - e * 5) * 2;
    int s = __ldg(src + e);
    int d = __ldg(dst + e);
    const float4* hp = reinterpret_cast<const float4*>(g_h2s + (size_t)s * F2) + c;
    float*        ap = g_agg2 + (size_t)d * F2 + c * 4;
    float4 v0 = hp[0];
    float4 v1 = hp[1];
    red_add_v4(ap,     v0);
    red_add_v4(ap + 4, v1);
}

// out = relu(inv_d * (agg2 + h2s))
__global__ __launch_bounds__(256) void final_kernel(float* __restrict__ out) {
    int i = blockIdx.x * blockDim.x + threadIdx.x;
    const int total = NN * (F2 / 4);
    if (i >= total) return;
    int node = i / 10;
    float inv_d = inv_sqrt_deg(node);
    float4 a = reinterpret_cast<const float4*>(g_agg2)[i];
    float4 h = reinterpret_cast<const float4*>(g_h2s)[i];
    float4 r;
    r.x = fmaxf(inv_d * (a.x + h.x), 0.f);
    r.y = fmaxf(inv_d * (a.y + h.y), 0.f);
    r.z = fmaxf(inv_d * (a.z + h.z), 0.f);
    r.w = fmaxf(inv_d * (a.w + h.w), 0.f);
    reinterpret_cast<float4*>(out)[i] = r;
}

// ---------------- launch ----------------------------------------------------
extern "C" void kernel_launch(void* const* d_in, const int* in_sizes, int n_in,
                              void* d_out, int out_size) {
    const float* x  = (const float*)d_in[0];   // [N,128]
    const int*   ei = (const int*)  d_in[1];   // [2,E]
    const float* W1 = (const float*)d_in[2];   // [128,64]
    const float* W2 = (const float*)d_in[3];   // [64,40]
    float* out = (float*)d_out;

    int E = in_sizes[1] / 2;
    const int* src = ei;
    const int* dst = ei + E;

    // 1. zero deg
    zero_kernel<<<(NN + 255) / 256, 256>>>();
    // 2. degree histogram (2 edges/thread)
    deg_kernel<<<(E/2 + 255) / 256, 256>>>(dst, E);
    // 3. h1s = (x @ W1) * rsqrt(deg+1)  (also zeros agg1)
    gemm1_kernel<<<(NN + 127) / 128, 128>>>(x, W1);
    // 4. layer-1 edge scatter  <-- profiled launch
    scatter1_kernel<<<(E * 8 + 255) / 256, 256>>>(src, dst, E);
    // 5. relu + self + GEMM2 -> h2s (also zeros agg2)
    fuse2_kernel<<<(NN + 255) / 256, 256>>>(W2);
    // 6. layer-2 edge scatter
    scatter2_kernel<<<(E * 5 + 255) / 256, 256>>>(src, dst, E);
    // 7. final relu -> d_out
    final_kernel<<<(NN * (F2/4) + 255) / 256, 256>>>(out);
}

// round 13
// speedup vs baseline: 1.8211x; 1.1815x over previous
#include <cuda_runtime.h>
#include <stdint.h>

// Problem constants (fixed by the dataset)
#define NN 100000      // nodes
#define F0 128
#define F1 64
#define F2 40

// ---------------- scratch (static device globals; allocation-free) ----------
__device__ __align__(16) float g_h1s [NN * F1];   // (x @ W1) * invsqrt[row]
__device__ __align__(16) float g_agg1[NN * F1];   // sum of h1s[src] per dst
__device__ __align__(16) float g_h2s [NN * F2];   // (out1 @ W2) * invsqrt[row]
__device__ __align__(16) float g_agg2[NN * F2];   // sum of h2s[src] per dst
__device__ int   g_deg[NN];

// ---------------- helpers ---------------------------------------------------
__device__ __forceinline__ void red_add_v4(float* addr, float4 v) {
    asm volatile("red.global.add.v4.f32 [%0], {%1, %2, %3, %4};"
                 :: "l"(addr), "f"(v.x), "f"(v.y), "f"(v.z), "f"(v.w)
                 : "memory");
}
__device__ __forceinline__ float inv_sqrt_deg(int node) {
    return rsqrtf((float)(g_deg[node] + 1));
}

// ---------------- kernels ---------------------------------------------------

// 1st launch: zero deg counters (agg zeroing folded into gemm1/fuse2).
__global__ void zero_kernel() {
    int i = blockIdx.x * blockDim.x + threadIdx.x;
    if (i < NN) g_deg[i] = 0;
}

// 2nd launch: degree histogram over dst; 2 edges per thread.
__global__ void deg_kernel(const int* __restrict__ dst, int E) {
    int i = (blockIdx.x * blockDim.x + threadIdx.x) * 2;
    if (i + 1 < E) {
        int2 d = *reinterpret_cast<const int2*>(dst + i);
        atomicAdd(&g_deg[d.x], 1);
        atomicAdd(&g_deg[d.y], 1);
    } else if (i < E) {
        atomicAdd(&g_deg[dst[i]], 1);
    }
}

// 3rd launch: h1s = (x @ W1) * rsqrt(deg+1)  (verified R10 8x8-tile GEMM).
// Epilogue also zeros the matching agg1 slots.
__global__ __launch_bounds__(128) void gemm1_kernel(const float* __restrict__ x,
                                                    const float* __restrict__ W1) {
    __shared__ float sX[32][132];           // [k_local][row 0..127], padded pitch
    __shared__ float sW[32 * F1];           // [k_local][col], 8 KB
    int tid = threadIdx.x;
    int row0 = blockIdx.x * 128;

    int tx = tid & 7;                       // col groups: tx*4 and 32+tx*4
    int ty = tid >> 3;                      // row groups: ty*4 and 64+ty*4

    float acc[8][8];
    #pragma unroll
    for (int r = 0; r < 8; ++r)
        #pragma unroll
        for (int c = 0; c < 8; ++c) acc[r][c] = 0.f;

    #pragma unroll
    for (int kc = 0; kc < 4; ++kc) {
        int k0 = kc * 32;

        const float4* w4g = reinterpret_cast<const float4*>(W1 + k0 * F1);
        #pragma unroll
        for (int i = 0; i < 4; ++i)
            reinterpret_cast<float4*>(sW)[tid + i * 128] = w4g[tid + i * 128];

        #pragma unroll
        for (int i = 0; i < 8; ++i) {
            int idx = tid + i * 128;
            int r   = idx >> 3;
            int k4  = idx & 7;
            int rr = row0 + r; if (rr >= NN) rr = NN - 1;
            float4 v = reinterpret_cast<const float4*>(
                           x + (size_t)rr * F0 + k0)[k4];
            sX[k4 * 4 + 0][r] = v.x;
            sX[k4 * 4 + 1][r] = v.y;
            sX[k4 * 4 + 2][r] = v.z;
            sX[k4 * 4 + 3][r] = v.w;
        }
        __syncthreads();

        #pragma unroll 2
        for (int k = 0; k < 32; ++k) {
            float4 xv0 = *reinterpret_cast<const float4*>(&sX[k][ty * 4]);
            float4 xv1 = *reinterpret_cast<const float4*>(&sX[k][64 + ty * 4]);
            float4 wv0 = *reinterpret_cast<const float4*>(&sW[k * F1 + tx * 4]);
            float4 wv1 = *reinterpret_cast<const float4*>(&sW[k * F1 + 32 + tx * 4]);
            float xa[8] = {xv0.x, xv0.y, xv0.z, xv0.w, xv1.x, xv1.y, xv1.z, xv1.w};
            float wa[8] = {wv0.x, wv0.y, wv0.z, wv0.w, wv1.x, wv1.y, wv1.z, wv1.w};
            #pragma unroll
            for (int r = 0; r < 8; ++r)
                #pragma unroll
                for (int c = 0; c < 8; ++c)
                    acc[r][c] = fmaf(xa[r], wa[c], acc[r][c]);
        }
        __syncthreads();
    }

    float4 z = make_float4(0.f, 0.f, 0.f, 0.f);
    #pragma unroll
    for (int r = 0; r < 8; ++r) {
        int rr = row0 + ((r < 4) ? (ty * 4 + r) : (64 + ty * 4 + r - 4));
        if (rr < NN) {
            float sc = inv_sqrt_deg(rr);
            float* hb = g_h1s  + (size_t)rr * F1;
            float* ab = g_agg1 + (size_t)rr * F1;
            *reinterpret_cast<float4*>(hb + tx * 4) =
                make_float4(acc[r][0]*sc, acc[r][1]*sc, acc[r][2]*sc, acc[r][3]*sc);
            *reinterpret_cast<float4*>(hb + 32 + tx * 4) =
                make_float4(acc[r][4]*sc, acc[r][5]*sc, acc[r][6]*sc, acc[r][7]*sc);
            *reinterpret_cast<float4*>(ab + tx * 4)      = z;
            *reinterpret_cast<float4*>(ab + 32 + tx * 4) = z;
        }
    }
}

// 4th launch (PROFILED): layer-1 scatter agg1[dst] += h1s[src].
// 8 threads/edge, SPLIT-HALF chunks: thread c handles float4 c (line 0) and
// float4 c+8 (line 1). Every warp-wide LDG.128/RED.128 touches only 4 cache
// lines (was 8) -> halves L1tex wavefronts vs the interleaved-pair layout.
__global__ __launch_bounds__(256) void scatter1_kernel(const int* __restrict__ src,
                                                       const int* __restrict__ dst, int E) {
    int i = blockIdx.x * blockDim.x + threadIdx.x;
    int total = E * 8;
    if (i >= total) return;
    int e = i >> 3;
    int c = i & 7;                 // float4 index in line 0; c+8 in line 1
    int s = __ldg(src + e);
    int d = __ldg(dst + e);
    const float4* hp = reinterpret_cast<const float4*>(g_h1s + (size_t)s * F1) + c;
    float*        ap = g_agg1 + (size_t)d * F1 + c * 4;
    float4 v0 = hp[0];             // float4[c]
    float4 v1 = hp[8];             // float4[c+8]
    red_add_v4(ap,      v0);
    red_add_v4(ap + 32, v1);       // +8 float4 = +32 floats
}

// out1 = relu(inv_d * (agg1 + h1s));  h2s = (out1 @ W2) * inv_d.
// Also zeros this row's agg2 slots (runs before scatter2).
__global__ __launch_bounds__(256) void fuse2_kernel(const float* __restrict__ W2) {
    __shared__ float sW[F1 * F2];
    int tid = threadIdx.x;
    for (int i = tid; i < F1 * F2; i += 256) sW[i] = W2[i];
    __syncthreads();

    int row = blockIdx.x * 256 + tid;
    if (row >= NN) return;

    float inv_d = inv_sqrt_deg(row);

    float o[F1];
    const float4* ag = reinterpret_cast<const float4*>(g_agg1 + (size_t)row * F1);
    const float4* hr = reinterpret_cast<const float4*>(g_h1s  + (size_t)row * F1);
    #pragma unroll
    for (int j = 0; j < F1 / 4; ++j) {
        float4 a = ag[j];
        float4 h = hr[j];
        o[4*j+0] = fmaxf(inv_d * (a.x + h.x), 0.f);
        o[4*j+1] = fmaxf(inv_d * (a.y + h.y), 0.f);
        o[4*j+2] = fmaxf(inv_d * (a.z + h.z), 0.f);
        o[4*j+3] = fmaxf(inv_d * (a.w + h.w), 0.f);
    }

    float acc[F2];
    #pragma unroll
    for (int j = 0; j < F2; ++j) acc[j] = 0.f;

    #pragma unroll 4
    for (int k = 0; k < F1; ++k) {
        float ov = o[k];
        const float4* w4 = reinterpret_cast<const float4*>(sW + k * F2);
        #pragma unroll
        for (int j = 0; j < F2 / 4; ++j) {
            float4 w = w4[j];
            acc[4*j+0] = fmaf(ov, w.x, acc[4*j+0]);
            acc[4*j+1] = fmaf(ov, w.y, acc[4*j+1]);
            acc[4*j+2] = fmaf(ov, w.z, acc[4*j+2]);
            acc[4*j+3] = fmaf(ov, w.w, acc[4*j+3]);
        }
    }
    float4* out = reinterpret_cast<float4*>(g_h2s + (size_t)row * F2);
    float4* az  = reinterpret_cast<float4*>(g_agg2 + (size_t)row * F2);
    float4 z = make_float4(0.f, 0.f, 0.f, 0.f);
    #pragma unroll
    for (int j = 0; j < F2 / 4; ++j) {
        out[j] = make_float4(acc[4*j]*inv_d, acc[4*j+1]*inv_d,
                             acc[4*j+2]*inv_d, acc[4*j+3]*inv_d);
        az[j] = z;
    }
}

// Layer-2 scatter: agg2[dst] += h2s[src].  5 threads/edge, split-half chunks:
// thread c handles float4 c (bytes 0-80) and float4 c+5 (bytes 80-160) so each
// warp-wide access covers a contiguous half-row range.
__global__ __launch_bounds__(256) void scatter2_kernel(const int* __restrict__ src,
                                                       const int* __restrict__ dst, int E) {
    int i = blockIdx.x * blockDim.x + threadIdx.x;
    int total = E * 5;
    if (i >= total) return;
    int e = i / 5;
    int c = i - e * 5;             // 0..4
    int s = __ldg(src + e);
    int d = __ldg(dst + e);
    const float4* hp = reinterpret_cast<const float4*>(g_h2s + (size_t)s * F2) + c;
    float*        ap = g_agg2 + (size_t)d * F2 + c * 4;
    float4 v0 = hp[0];             // float4[c]
    float4 v1 = hp[5];             // float4[c+5]
    red_add_v4(ap,      v0);
    red_add_v4(ap + 20, v1);       // +5 float4 = +20 floats
}

// out = relu(inv_d * (agg2 + h2s))
__global__ __launch_bounds__(256) void final_kernel(float* __restrict__ out) {
    int i = blockIdx.x * blockDim.x + threadIdx.x;
    const int total = NN * (F2 / 4);
    if (i >= total) return;
    int node = i / 10;
    float inv_d = inv_sqrt_deg(node);
    float4 a = reinterpret_cast<const float4*>(g_agg2)[i];
    float4 h = reinterpret_cast<const float4*>(g_h2s)[i];
    float4 r;
    r.x = fmaxf(inv_d * (a.x + h.x), 0.f);
    r.y = fmaxf(inv_d * (a.y + h.y), 0.f);
    r.z = fmaxf(inv_d * (a.z + h.z), 0.f);
    r.w = fmaxf(inv_d * (a.w + h.w), 0.f);
    reinterpret_cast<float4*>(out)[i] = r;
}

// ---------------- launch ----------------------------------------------------
extern "C" void kernel_launch(void* const* d_in, const int* in_sizes, int n_in,
                              void* d_out, int out_size) {
    const float* x  = (const float*)d_in[0];   // [N,128]
    const int*   ei = (const int*)  d_in[1];   // [2,E]
    const float* W1 = (const float*)d_in[2];   // [128,64]
    const float* W2 = (const float*)d_in[3];   // [64,40]
    float* out = (float*)d_out;

    int E = in_sizes[1] / 2;
    const int* src = ei;
    const int* dst = ei + E;

    // 1. zero deg
    zero_kernel<<<(NN + 255) / 256, 256>>>();
    // 2. degree histogram (2 edges/thread)
    deg_kernel<<<(E/2 + 255) / 256, 256>>>(dst, E);
    // 3. h1s = (x @ W1) * rsqrt(deg+1)  (also zeros agg1)
    gemm1_kernel<<<(NN + 127) / 128, 128>>>(x, W1);
    // 4. layer-1 edge scatter (split-half lines)  <-- profiled launch
    scatter1_kernel<<<(E * 8 + 255) / 256, 256>>>(src, dst, E);
    // 5. relu + self + GEMM2 -> h2s (also zeros agg2)
    fuse2_kernel<<<(NN + 255) / 256, 256>>>(W2);
    // 6. layer-2 edge scatter (split-half)
    scatter2_kernel<<<(E * 5 + 255) / 256, 256>>>(src, dst, E);
    // 7. final relu -> d_out
    final_kernel<<<(NN * (F2/4) + 255) / 256, 256>>>(out);
}